// round 10
// baseline (speedup 1.0000x reference)
#include <cuda_runtime.h>
#include <cuda_bf16.h>
#include <cstdint>
#include <cstddef>

#define NN 16384
#define HD 64

// ---------------- static device scratch (no runtime allocation) ----------------
__device__ __nv_bfloat16 g_adjT_hi[(size_t)NN * NN];   // adjT[i][j] hi plane, j contiguous
__device__ __nv_bfloat16 g_adjT_lo[(size_t)NN * NN];   // residual plane
__device__ __nv_bfloat16 g_BhiT[HD * NN];              // hr^T hi [f][j]
__device__ __nv_bfloat16 g_BloT[HD * NN];              // hr^T lo [f][j]
__device__ float         g_root[(size_t)NN * HD];      // b + h @ W_root^T  [j][f]
__device__ float         g_h[(size_t)NN * HD];         // layer intermediate [j][f]

// ---------------- helpers ----------------
__device__ __forceinline__ uint32_t smem_u32(const void* p) {
    uint32_t a;
    asm("{ .reg .u64 t; cvta.to.shared.u64 t, %1; cvt.u32.u64 %0, t; }" : "=r"(a) : "l"(p));
    return a;
}
__device__ __forceinline__ void cp16(uint32_t s, const void* g) {
    asm volatile("cp.async.cg.shared.global [%0], [%1], 16;"
                 :: "r"(s), "l"(__cvta_generic_to_global(g)) : "memory");
}
#define CP_COMMIT() asm volatile("cp.async.commit_group;" ::: "memory")
#define CP_WAIT_2() asm volatile("cp.async.wait_group 2;" ::: "memory")

__device__ __forceinline__ uint32_t sw128(uint32_t off) { return off ^ ((off >> 3) & 0x70); }

__device__ __forceinline__ void ldsm_x4(uint32_t addr, uint32_t& r0, uint32_t& r1,
                                        uint32_t& r2, uint32_t& r3) {
    asm volatile("ldmatrix.sync.aligned.m8n8.x4.shared.b16 {%0,%1,%2,%3}, [%4];"
                 : "=r"(r0), "=r"(r1), "=r"(r2), "=r"(r3) : "r"(addr));
}

// D += A(16x16 bf16) * B(16x8 bf16), fp32 accumulate
__device__ __forceinline__ void mma16816(float* c, const uint32_t* a, uint32_t b0, uint32_t b1) {
    asm volatile(
        "mma.sync.aligned.m16n8k16.row.col.f32.bf16.bf16.f32 "
        "{%0,%1,%2,%3}, {%4,%5,%6,%7}, {%8,%9}, {%0,%1,%2,%3};"
        : "+f"(c[0]), "+f"(c[1]), "+f"(c[2]), "+f"(c[3])
        : "r"(a[0]), "r"(a[1]), "r"(a[2]), "r"(a[3]), "r"(b0), "r"(b1));
}

// ---------------- kernel 1: transpose + split adj ----------------
// adj[j][i] fp32 -> adjT hi/lo bf16 planes [i][j], j contiguous
__global__ void __launch_bounds__(256) transpose_split_kernel(const float* __restrict__ adj) {
    __shared__ float tile[64][33];   // [j_local][i_local]
    int i0 = blockIdx.x * 32;
    int j0 = blockIdx.y * 64;
    int tx = threadIdx.x;            // 0..31
    int ty = threadIdx.y;            // 0..7
#pragma unroll
    for (int r = 0; r < 8; ++r) {
        int jl = ty + r * 8;
        tile[jl][tx] = adj[(size_t)(j0 + jl) * NN + i0 + tx];
    }
    __syncthreads();
#pragma unroll
    for (int r = 0; r < 4; ++r) {
        int il = ty + r * 8;
        float v0 = tile[2 * tx][il];
        float v1 = tile[2 * tx + 1][il];
        __nv_bfloat16 h0 = __float2bfloat16(v0);
        __nv_bfloat16 h1 = __float2bfloat16(v1);
        __nv_bfloat16 l0 = __float2bfloat16(v0 - __bfloat162float(h0));
        __nv_bfloat16 l1 = __float2bfloat16(v1 - __bfloat162float(h1));
        size_t o = (size_t)(i0 + il) * NN + j0 + 2 * tx;
        *reinterpret_cast<__nv_bfloat162*>(&g_adjT_hi[o]) = __halves2bfloat162(h0, h1);
        *reinterpret_cast<__nv_bfloat162*>(&g_adjT_lo[o]) = __halves2bfloat162(l0, l1);
    }
}

// ---------------- kernel 2: hr^T planes + root term ----------------
template <int F>
__global__ void __launch_bounds__(256) relroot_kernel(
    const float* __restrict__ xsrc, int use_x,
    const float* __restrict__ Wrel, const float* __restrict__ bias,
    const float* __restrict__ Wroot)
{
    extern __shared__ float sm[];
    float* hs = sm;                      // [64][F+1]
    float* wr = sm + 64 * (F + 1);
    float* wo = wr + 64 * (F + 1);
    const float* h = use_x ? xsrc : g_h;
    int j0 = blockIdx.x * 64;

    for (int idx = threadIdx.x; idx < 64 * F; idx += 256) {
        int r = idx / F, c = idx % F;
        hs[r * (F + 1) + c] = h[(size_t)(j0 + r) * F + c];
        wr[r * (F + 1) + c] = Wrel[r * F + c];
        wo[r * (F + 1) + c] = Wroot[r * F + c];
    }
    __syncthreads();

    int f  = threadIdx.x & 63;
    int jg = threadIdx.x >> 6;           // 0..3 -> 16 nodes each
    float ar[16], ao[16];
#pragma unroll
    for (int k = 0; k < 16; ++k) { ar[k] = 0.f; ao[k] = 0.f; }

    const float* wrf = wr + f * (F + 1);
    const float* wof = wo + f * (F + 1);
    const float* hb  = hs + (jg * 16) * (F + 1);
#pragma unroll 4
    for (int c = 0; c < F; ++c) {
        float a = wrf[c];
        float b = wof[c];
#pragma unroll
        for (int k = 0; k < 16; ++k) {
            float x = hb[k * (F + 1) + c];
            ar[k] = fmaf(a, x, ar[k]);
            ao[k] = fmaf(b, x, ao[k]);
        }
    }
    float bf = bias[f];
#pragma unroll
    for (int k = 0; k < 16; ++k) {
        int j = j0 + jg * 16 + k;
        float v = ar[k];
        __nv_bfloat16 hi = __float2bfloat16(v);
        __nv_bfloat16 lo = __float2bfloat16(v - __bfloat162float(hi));
        g_BhiT[f * NN + j] = hi;
        g_BloT[f * NN + j] = lo;
        g_root[(size_t)j * HD + f] = ao[k] + bf;
    }
}

// ---------------- kernel 3: aggregation out = relu(adjT@hr + root) ----------------
// CTA: 128 i x 64 f, 256 threads (8 warps, warp tile 64 i x 16 f).
// 4-stage cp.async pipeline, 64-wide K tiles, mma.sync m16n8k16 bf16, split hi/lo.
#define NSTAGE 4
#define STAGE_BYTES 49152u
#define A_HI_OFF 0u
#define A_LO_OFF 16384u
#define B_HI_OFF 32768u
#define B_LO_OFF 40960u
#define NITER 256                          // 16384 / 64
#define SMEM_TOTAL_MMA (NSTAGE * STAGE_BYTES)   // 196608

__device__ __forceinline__ void fill_stage(uint32_t sb, int s, int jt, int tid, int ibase) {
    uint32_t SB = sb + (uint32_t)s * STAGE_BYTES;
    size_t j0 = (size_t)jt * 64;
    // A planes: 128 rows x 128B (64 bf16), SW128 swizzled; 1024 16B chunks/plane
#pragma unroll
    for (int q = tid; q < 1024; q += 256) {
        int row = q >> 3;
        uint32_t sw = sw128((uint32_t)q << 4);
        size_t off = (size_t)(ibase + row) * NN + j0 + (size_t)((q & 7) << 3);
        cp16(SB + A_HI_OFF + sw, g_adjT_hi + off);
        cp16(SB + A_LO_OFF + sw, g_adjT_lo + off);
    }
    // B planes: 64 rows x 128B; 512 chunks/plane
#pragma unroll
    for (int q = tid; q < 512; q += 256) {
        int row = q >> 3;
        uint32_t sw = sw128((uint32_t)q << 4);
        size_t off = (size_t)row * NN + j0 + (size_t)((q & 7) << 3);
        cp16(SB + B_HI_OFF + sw, g_BhiT + off);
        cp16(SB + B_LO_OFF + sw, g_BloT + off);
    }
}

__global__ void __launch_bounds__(256, 1) gnn_agg_kernel(float* __restrict__ dout, int final_layer) {
    extern __shared__ char smem[];
    uint32_t sb = smem_u32(smem);
    int tid  = threadIdx.x;
    int lane = tid & 31;
    int wid  = tid >> 5;
    int wi   = wid & 1;        // i-block (64 rows each)
    int wf   = wid >> 1;       // f-block (16 cols each)
    int ibase = blockIdx.x * 128;

    int gid = lane >> 2;       // 0..7
    int tig = lane & 3;        // 0..3

    // ldmatrix thread -> (row within 16, k-half) mapping (same for A and B^T)
    int lrow  = lane & 15;             // row within the 16-row tile
    int lkoff = (lane >= 16) ? 16 : 0; // byte offset for k 8..15 half

    float acc[4][2][4];
#pragma unroll
    for (int mt = 0; mt < 4; ++mt)
#pragma unroll
        for (int nt = 0; nt < 2; ++nt)
#pragma unroll
            for (int c = 0; c < 4; ++c) acc[mt][nt][c] = 0.f;

    // prologue: fill stages 0..2
    for (int p = 0; p < NSTAGE - 1; ++p) { fill_stage(sb, p, p, tid, ibase); CP_COMMIT(); }

    for (int it = 0; it < NITER; ++it) {
        int s = it & 3;
        CP_WAIT_2();
        __syncthreads();                     // stage s ready for all warps; stage (it-1)&3 free

        uint32_t SB  = sb + (uint32_t)s * STAGE_BYTES;
        uint32_t bba = SB + ((uint32_t)(wf * 16 + lrow) << 7) + (uint32_t)lkoff;  // B row base

#pragma unroll
        for (int k16 = 0; k16 < 4; ++k16) {
            uint32_t kb = (uint32_t)(k16 << 5);  // k16*16 bf16 = 32 bytes
            // B fragments: r0,r1 = b0 of n-tile 0/1 ; r2,r3 = b1 of n-tile 0/1
            uint32_t bh0, bh1, bh2, bh3, bl0, bl1, bl2, bl3;
            {
                uint32_t off = sw128(bba - SB + kb);
                ldsm_x4(SB + B_HI_OFF + off, bh0, bh1, bh2, bh3);
                ldsm_x4(SB + B_LO_OFF + off, bl0, bl1, bl2, bl3);
            }
#pragma unroll
            for (int mt = 0; mt < 4; ++mt) {
                int arow = wi * 64 + mt * 16 + lrow;
                uint32_t aoff = sw128(((uint32_t)arow << 7) + kb + (uint32_t)lkoff);
                uint32_t ah[4], al[4];
                ldsm_x4(SB + A_HI_OFF + aoff, ah[0], ah[1], ah[2], ah[3]);
                ldsm_x4(SB + A_LO_OFF + aoff, al[0], al[1], al[2], al[3]);
                // n-tile 0: b regs (r0, r2) ; n-tile 1: (r1, r3)
                mma16816(acc[mt][0], ah, bh0, bh2);
                mma16816(acc[mt][0], ah, bl0, bl2);
                mma16816(acc[mt][0], al, bh0, bh2);
                mma16816(acc[mt][1], ah, bh1, bh3);
                mma16816(acc[mt][1], ah, bl1, bl3);
                mma16816(acc[mt][1], al, bh1, bh3);
            }
        }

        int nf = it + NSTAGE - 1;
        __syncthreads();                     // all warps done reading stage s... (protects nf&3 == (it-1)&3? no: nf&3==(it+3)&3==(it-1)&3, freed by the sync at top of this iter)
        if (nf < NITER) fill_stage(sb, nf & 3, nf, tid, ibase);
        CP_COMMIT();                         // exactly one group per iteration
    }

    // epilogue: acc + root, relu, store
    float* obase = final_layer ? dout : g_h;
#pragma unroll
    for (int mt = 0; mt < 4; ++mt) {
#pragma unroll
        for (int nt = 0; nt < 2; ++nt) {
            int i0 = ibase + wi * 64 + mt * 16 + gid;
            int f0 = wf * 16 + nt * 8 + tig * 2;
            const float* r0 = g_root + (size_t)i0 * HD + f0;
            const float* r1 = g_root + (size_t)(i0 + 8) * HD + f0;
            float v00 = acc[mt][nt][0] + r0[0];
            float v01 = acc[mt][nt][1] + r0[1];
            float v10 = acc[mt][nt][2] + r1[0];
            float v11 = acc[mt][nt][3] + r1[1];
            float* o0 = obase + (size_t)i0 * HD + f0;
            float* o1 = obase + (size_t)(i0 + 8) * HD + f0;
            o0[0] = v00 > 0.f ? v00 : 0.f;
            o0[1] = v01 > 0.f ? v01 : 0.f;
            o1[0] = v10 > 0.f ? v10 : 0.f;
            o1[1] = v11 > 0.f ? v11 : 0.f;
        }
    }
}

// ---------------- launch ----------------
extern "C" void kernel_launch(void* const* d_in, const int* in_sizes, int n_in,
                              void* d_out, int out_size) {
    const float* X      = (const float*)d_in[0];
    const float* adj    = (const float*)d_in[1];
    const float* Wrel0  = (const float*)d_in[2];
    const float* brel0  = (const float*)d_in[3];
    const float* Wroot0 = (const float*)d_in[4];
    const float* Wrel1  = (const float*)d_in[5];
    const float* brel1  = (const float*)d_in[6];
    const float* Wroot1 = (const float*)d_in[7];
    const float* Wrel2  = (const float*)d_in[8];
    const float* brel2  = (const float*)d_in[9];
    const float* Wroot2 = (const float*)d_in[10];
    float* out = (float*)d_out;

    const int smem256 = 3 * 64 * 257 * (int)sizeof(float);   // 197376
    const int smem64  = 3 * 64 * 65  * (int)sizeof(float);   // 49920
    cudaFuncSetAttribute((void*)relroot_kernel<256>, cudaFuncAttributeMaxDynamicSharedMemorySize, smem256);
    cudaFuncSetAttribute((void*)relroot_kernel<64>,  cudaFuncAttributeMaxDynamicSharedMemorySize, smem64);
    cudaFuncSetAttribute((void*)gnn_agg_kernel,      cudaFuncAttributeMaxDynamicSharedMemorySize, (int)SMEM_TOTAL_MMA);

    transpose_split_kernel<<<dim3(NN / 32, NN / 64), dim3(32, 8)>>>(adj);

    relroot_kernel<256><<<NN / 64, 256, smem256>>>(X, 1, Wrel0, brel0, Wroot0);
    gnn_agg_kernel<<<NN / 128, 256, SMEM_TOTAL_MMA>>>(out, 0);

    relroot_kernel<64><<<NN / 64, 256, smem64>>>(nullptr, 0, Wrel1, brel1, Wroot1);
    gnn_agg_kernel<<<NN / 128, 256, SMEM_TOTAL_MMA>>>(out, 0);

    relroot_kernel<64><<<NN / 64, 256, smem64>>>(nullptr, 0, Wrel2, brel2, Wroot2);
    gnn_agg_kernel<<<NN / 128, 256, SMEM_TOTAL_MMA>>>(out, 1);
}